// round 1
// baseline (speedup 1.0000x reference)
#include <cuda_runtime.h>
#include <cuda_bf16.h>

#define BATCH 2
#define SEQ   2048
#define EMB   1024
#define HEADS 16
#define HDIM  64
#define MROWS (BATCH*SEQ)   // 4096
#define NQKV  (3*EMB)       // 3072

// Scratch (device globals: no allocation allowed in kernel_launch)
__device__ float g_q[BATCH*HEADS*SEQ*HDIM];     // [b,h,t,d]
__device__ float g_k[BATCH*HEADS*SEQ*HDIM];
__device__ float g_v[BATCH*HEADS*SEQ*HDIM];
__device__ float g_attn[BATCH*SEQ*EMB];          // [b,t,(h d)]

// ---------------------------------------------------------------------------
// QKV projection: C[m,n] = sum_k x[m,k] * w_qkv[n,k], scattered into g_q/k/v.
// Channel decode follows reshape (b,t,d,3,h): n -> di=n/48, ki=(n/16)%3, hi=n%16
// ---------------------------------------------------------------------------
__global__ __launch_bounds__(256) void gemm_qkv_kernel(const float* __restrict__ A,
                                                       const float* __restrict__ W) {
    __shared__ float As[8][128];
    __shared__ float Ws[8][128];
    const int K = EMB;
    int tid  = threadIdx.x;
    int m0   = blockIdx.y * 128;
    int n0   = blockIdx.x * 128;
    int lrow = tid >> 1;
    int lcol = (tid & 1) * 4;
    const float* Ag = A + (size_t)(m0 + lrow) * K + lcol;
    const float* Wg = W + (size_t)(n0 + lrow) * K + lcol;
    int tx = tid & 15, ty = tid >> 4;

    float acc[8][8];
#pragma unroll
    for (int i = 0; i < 8; i++)
#pragma unroll
        for (int j = 0; j < 8; j++) acc[i][j] = 0.0f;

    for (int k0 = 0; k0 < K; k0 += 8) {
        float4 a4 = *(const float4*)(Ag + k0);
        float4 w4 = *(const float4*)(Wg + k0);
        __syncthreads();
        As[lcol+0][lrow] = a4.x; As[lcol+1][lrow] = a4.y;
        As[lcol+2][lrow] = a4.z; As[lcol+3][lrow] = a4.w;
        Ws[lcol+0][lrow] = w4.x; Ws[lcol+1][lrow] = w4.y;
        Ws[lcol+2][lrow] = w4.z; Ws[lcol+3][lrow] = w4.w;
        __syncthreads();
#pragma unroll
        for (int kk = 0; kk < 8; kk++) {
            float4 a0 = *(const float4*)&As[kk][ty*8];
            float4 a1 = *(const float4*)&As[kk][ty*8+4];
            float4 b0 = *(const float4*)&Ws[kk][tx*8];
            float4 b1 = *(const float4*)&Ws[kk][tx*8+4];
            float ar[8] = {a0.x,a0.y,a0.z,a0.w,a1.x,a1.y,a1.z,a1.w};
            float br[8] = {b0.x,b0.y,b0.z,b0.w,b1.x,b1.y,b1.z,b1.w};
#pragma unroll
            for (int i = 0; i < 8; i++)
#pragma unroll
                for (int j = 0; j < 8; j++)
                    acc[i][j] += ar[i] * br[j];
        }
    }

    // Scatter epilogue into [b,h,t,d] Q/K/V buffers
#pragma unroll
    for (int i = 0; i < 8; i++) {
        int m  = m0 + ty*8 + i;
        int bb = m / SEQ;
        int t  = m % SEQ;
#pragma unroll
        for (int j = 0; j < 8; j++) {
            int n  = n0 + tx*8 + j;
            int di = n / 48;
            int ki = (n >> 4) % 3;
            int hi = n & 15;
            size_t dst = ((size_t)(bb*HEADS + hi) * SEQ + t) * HDIM + di;
            float v = acc[i][j];
            if (ki == 0)      g_q[dst] = v;
            else if (ki == 1) g_k[dst] = v;
            else              g_v[dst] = v;
        }
    }
}

// ---------------------------------------------------------------------------
// Flash attention: one thread per query row. q[64] and o[64] in registers,
// K/V tiles (16 x 64) in smem (broadcast reads), private online softmax.
// Scores are MULTIPLIED by sqrt(d)=8 per the reference.
// ---------------------------------------------------------------------------
__global__ __launch_bounds__(128, 2) void attn_kernel() {
    __shared__ float Ks[16][64];
    __shared__ float Vs[16][64];

    int bh  = blockIdx.y;                       // 0..31 = b*16 + h
    int row = blockIdx.x * 128 + threadIdx.x;   // query row within (b,h)

    const float* qptr  = g_q + ((size_t)bh * SEQ + row) * HDIM;
    const float* kbase = g_k + (size_t)bh * SEQ * HDIM;
    const float* vbase = g_v + (size_t)bh * SEQ * HDIM;

    float q[HDIM];
#pragma unroll
    for (int i = 0; i < 16; i++) {
        float4 t4 = *(const float4*)(qptr + 4*i);
        q[4*i+0] = t4.x; q[4*i+1] = t4.y; q[4*i+2] = t4.z; q[4*i+3] = t4.w;
    }

    float o[HDIM];
#pragma unroll
    for (int d = 0; d < HDIM; d++) o[d] = 0.0f;
    float mrun = -1e30f;
    float lrun = 0.0f;

    for (int j0 = 0; j0 < SEQ; j0 += 16) {
        __syncthreads();
#pragma unroll
        for (int u = 0; u < 2; u++) {
            int idx = threadIdx.x + u * 128;    // 0..255 float4 slots
            int jj  = idx >> 4;
            int dd  = (idx & 15) * 4;
            *(float4*)&Ks[jj][dd] = *(const float4*)(kbase + (size_t)(j0+jj)*HDIM + dd);
            *(float4*)&Vs[jj][dd] = *(const float4*)(vbase + (size_t)(j0+jj)*HDIM + dd);
        }
        __syncthreads();

        float s[16];
#pragma unroll
        for (int j = 0; j < 16; j++) {
            const float4* K4 = (const float4*)Ks[j];
            float a0 = 0.f, a1 = 0.f, a2 = 0.f, a3 = 0.f;
#pragma unroll
            for (int d4 = 0; d4 < 16; d4++) {
                float4 kk = K4[d4];
                a0 += q[4*d4+0] * kk.x;
                a1 += q[4*d4+1] * kk.y;
                a2 += q[4*d4+2] * kk.z;
                a3 += q[4*d4+3] * kk.w;
            }
            s[j] = ((a0 + a1) + (a2 + a3)) * 8.0f;   // * sqrt(head_dim)
        }

        float tm = s[0];
#pragma unroll
        for (int j = 1; j < 16; j++) tm = fmaxf(tm, s[j]);
        float nm = fmaxf(mrun, tm);
        float corr = __expf(mrun - nm);
        lrun *= corr;
#pragma unroll
        for (int d = 0; d < HDIM; d++) o[d] *= corr;

#pragma unroll
        for (int j = 0; j < 16; j++) {
            float p = __expf(s[j] - nm);
            lrun += p;
            const float4* V4 = (const float4*)Vs[j];
#pragma unroll
            for (int d4 = 0; d4 < 16; d4++) {
                float4 vv = V4[d4];
                o[4*d4+0] += p * vv.x;
                o[4*d4+1] += p * vv.y;
                o[4*d4+2] += p * vv.z;
                o[4*d4+3] += p * vv.w;
            }
        }
        mrun = nm;
    }

    float inv = 1.0f / lrun;
    int bb = bh >> 4;
    int hi = bh & 15;
    float* dst = g_attn + ((size_t)bb * SEQ + row) * EMB + hi * HDIM;
#pragma unroll
    for (int d4 = 0; d4 < 16; d4++) {
        float4 r;
        r.x = o[4*d4+0] * inv; r.y = o[4*d4+1] * inv;
        r.z = o[4*d4+2] * inv; r.w = o[4*d4+3] * inv;
        *(float4*)(dst + 4*d4) = r;
    }
}

// ---------------------------------------------------------------------------
// Output projection: out[m,n] = sum_k g_attn[m,k] * w_out[n,k]
// ---------------------------------------------------------------------------
__global__ __launch_bounds__(256) void gemm_out_kernel(const float* __restrict__ W,
                                                       float* __restrict__ out) {
    __shared__ float As[8][128];
    __shared__ float Ws[8][128];
    const int K = EMB, N = EMB;
    int tid  = threadIdx.x;
    int m0   = blockIdx.y * 128;
    int n0   = blockIdx.x * 128;
    int lrow = tid >> 1;
    int lcol = (tid & 1) * 4;
    const float* Ag = g_attn + (size_t)(m0 + lrow) * K + lcol;
    const float* Wg = W      + (size_t)(n0 + lrow) * K + lcol;
    int tx = tid & 15, ty = tid >> 4;

    float acc[8][8];
#pragma unroll
    for (int i = 0; i < 8; i++)
#pragma unroll
        for (int j = 0; j < 8; j++) acc[i][j] = 0.0f;

    for (int k0 = 0; k0 < K; k0 += 8) {
        float4 a4 = *(const float4*)(Ag + k0);
        float4 w4 = *(const float4*)(Wg + k0);
        __syncthreads();
        As[lcol+0][lrow] = a4.x; As[lcol+1][lrow] = a4.y;
        As[lcol+2][lrow] = a4.z; As[lcol+3][lrow] = a4.w;
        Ws[lcol+0][lrow] = w4.x; Ws[lcol+1][lrow] = w4.y;
        Ws[lcol+2][lrow] = w4.z; Ws[lcol+3][lrow] = w4.w;
        __syncthreads();
#pragma unroll
        for (int kk = 0; kk < 8; kk++) {
            float4 a0 = *(const float4*)&As[kk][ty*8];
            float4 a1 = *(const float4*)&As[kk][ty*8+4];
            float4 b0 = *(const float4*)&Ws[kk][tx*8];
            float4 b1 = *(const float4*)&Ws[kk][tx*8+4];
            float ar[8] = {a0.x,a0.y,a0.z,a0.w,a1.x,a1.y,a1.z,a1.w};
            float br[8] = {b0.x,b0.y,b0.z,b0.w,b1.x,b1.y,b1.z,b1.w};
#pragma unroll
            for (int i = 0; i < 8; i++)
#pragma unroll
                for (int j = 0; j < 8; j++)
                    acc[i][j] += ar[i] * br[j];
        }
    }

#pragma unroll
    for (int i = 0; i < 8; i++) {
        int m = m0 + ty*8 + i;
        float* dst = out + (size_t)m * N + n0 + tx*8;
        float4 r0, r1;
        r0.x = acc[i][0]; r0.y = acc[i][1]; r0.z = acc[i][2]; r0.w = acc[i][3];
        r1.x = acc[i][4]; r1.y = acc[i][5]; r1.z = acc[i][6]; r1.w = acc[i][7];
        *(float4*)(dst + 0) = r0;
        *(float4*)(dst + 4) = r1;
    }
}

// ---------------------------------------------------------------------------
extern "C" void kernel_launch(void* const* d_in, const int* in_sizes, int n_in,
                              void* d_out, int out_size) {
    const float* x     = (const float*)d_in[0];   // [B,T,E]
    const float* w_qkv = (const float*)d_in[1];   // [3E,E]
    const float* w_out = (const float*)d_in[2];   // [E,E]
    float* out = (float*)d_out;                   // [B,T,E]

    // 1) QKV projection with fused head-split scatter
    gemm_qkv_kernel<<<dim3(NQKV/128, MROWS/128), 256>>>(x, w_qkv);

    // 2) Flash attention (one thread per query row)
    attn_kernel<<<dim3(SEQ/128, BATCH*HEADS), 128>>>();

    // 3) Output projection
    gemm_out_kernel<<<dim3(EMB/128, MROWS/128), 256>>>(w_out, out);
}

// round 2
// speedup vs baseline: 1.0838x; 1.0838x over previous
#include <cuda_runtime.h>
#include <cuda_bf16.h>

#define BATCH 2
#define SEQ   2048
#define EMB   1024
#define HEADS 16
#define HDIM  64
#define MROWS (BATCH*SEQ)   // 4096
#define NQKV  (3*EMB)       // 3072

typedef unsigned long long u64;

// Scratch (device globals: no allocation allowed in kernel_launch)
__device__ float g_q[BATCH*HEADS*SEQ*HDIM];     // [b,h,t,d]
__device__ float g_k[BATCH*HEADS*SEQ*HDIM];
__device__ float g_v[BATCH*HEADS*SEQ*HDIM];
__device__ float g_attn[BATCH*SEQ*EMB];          // [b,t,(h d)]

// ---- packed f32x2 helpers (sm_103a FFMA2 path) ----------------------------
__device__ __forceinline__ u64 bcast2(float v) {
    u64 r; unsigned u = __float_as_uint(v);
    asm("mov.b64 %0, {%1, %1};" : "=l"(r) : "r"(u));
    return r;
}
__device__ __forceinline__ u64 pack2(float lo, float hi) {
    u64 r; unsigned a = __float_as_uint(lo), b = __float_as_uint(hi);
    asm("mov.b64 %0, {%1, %2};" : "=l"(r) : "r"(a), "r"(b));
    return r;
}
__device__ __forceinline__ void fma2(u64& acc, u64 a, u64 b) {
    asm("fma.rn.f32x2 %0, %1, %2, %0;" : "+l"(acc) : "l"(a), "l"(b));
}
__device__ __forceinline__ void mul2(u64& d, u64 a) {
    asm("mul.rn.f32x2 %0, %0, %1;" : "+l"(d) : "l"(a));
}
__device__ __forceinline__ float2 unpk2(u64 v) {
    unsigned lo, hi;
    asm("mov.b64 {%0, %1}, %2;" : "=r"(lo), "=r"(hi) : "l"(v));
    float2 f; f.x = __uint_as_float(lo); f.y = __uint_as_float(hi);
    return f;
}

// ---------------------------------------------------------------------------
// QKV projection: C[m,n] = sum_k x[m,k] * w_qkv[n,k], scattered into g_q/k/v.
// Channel decode follows reshape (b,t,d,3,h): n -> di=n/48, ki=(n/16)%3, hi=n%16
// ---------------------------------------------------------------------------
__global__ __launch_bounds__(256) void gemm_qkv_kernel(const float* __restrict__ A,
                                                       const float* __restrict__ W) {
    __shared__ float As[8][128];
    __shared__ float Ws[8][128];
    const int K = EMB;
    int tid  = threadIdx.x;
    int m0   = blockIdx.y * 128;
    int n0   = blockIdx.x * 128;
    int lrow = tid >> 1;
    int lcol = (tid & 1) * 4;
    const float* Ag = A + (size_t)(m0 + lrow) * K + lcol;
    const float* Wg = W + (size_t)(n0 + lrow) * K + lcol;
    int tx = tid & 15, ty = tid >> 4;

    u64 acc2[8][4];
#pragma unroll
    for (int i = 0; i < 8; i++)
#pragma unroll
        for (int j = 0; j < 4; j++) acc2[i][j] = 0ull;

    for (int k0 = 0; k0 < K; k0 += 8) {
        float4 a4 = *(const float4*)(Ag + k0);
        float4 w4 = *(const float4*)(Wg + k0);
        __syncthreads();
        As[lcol+0][lrow] = a4.x; As[lcol+1][lrow] = a4.y;
        As[lcol+2][lrow] = a4.z; As[lcol+3][lrow] = a4.w;
        Ws[lcol+0][lrow] = w4.x; Ws[lcol+1][lrow] = w4.y;
        Ws[lcol+2][lrow] = w4.z; Ws[lcol+3][lrow] = w4.w;
        __syncthreads();
#pragma unroll
        for (int kk = 0; kk < 8; kk++) {
            float4 a0 = *(const float4*)&As[kk][ty*8];
            float4 a1 = *(const float4*)&As[kk][ty*8+4];
            ulonglong2 b0 = *(const ulonglong2*)&Ws[kk][tx*8];
            ulonglong2 b1 = *(const ulonglong2*)&Ws[kk][tx*8+4];
            u64 av[8] = {bcast2(a0.x), bcast2(a0.y), bcast2(a0.z), bcast2(a0.w),
                         bcast2(a1.x), bcast2(a1.y), bcast2(a1.z), bcast2(a1.w)};
            u64 bv[4] = {b0.x, b0.y, b1.x, b1.y};
#pragma unroll
            for (int i = 0; i < 8; i++)
#pragma unroll
                for (int j = 0; j < 4; j++)
                    fma2(acc2[i][j], av[i], bv[j]);
        }
    }

    // Scatter epilogue into [b,h,t,d] Q/K/V buffers
#pragma unroll
    for (int i = 0; i < 8; i++) {
        int m  = m0 + ty*8 + i;
        int bb = m / SEQ;
        int t  = m % SEQ;
        float c[8];
#pragma unroll
        for (int j = 0; j < 4; j++) {
            float2 f = unpk2(acc2[i][j]);
            c[2*j] = f.x; c[2*j+1] = f.y;
        }
#pragma unroll
        for (int j = 0; j < 8; j++) {
            int n  = n0 + tx*8 + j;
            int di = n / 48;
            int ki = (n >> 4) % 3;
            int hi = n & 15;
            size_t dst = ((size_t)(bb*HEADS + hi) * SEQ + t) * HDIM + di;
            float v = c[j];
            if (ki == 0)      g_q[dst] = v;
            else if (ki == 1) g_k[dst] = v;
            else              g_v[dst] = v;
        }
    }
}

// ---------------------------------------------------------------------------
// Flash attention: one thread per query row, f32x2-packed along head dim.
// Scores are MULTIPLIED by sqrt(d)=8 per the reference.
// ---------------------------------------------------------------------------
__global__ __launch_bounds__(128, 2) void attn_kernel() {
    __shared__ float Ks[16][64];
    __shared__ float Vs[16][64];

    int bh  = blockIdx.y;                       // 0..31 = b*16 + h
    int row = blockIdx.x * 128 + threadIdx.x;   // query row within (b,h)

    const float* qptr  = g_q + ((size_t)bh * SEQ + row) * HDIM;
    const float* kbase = g_k + (size_t)bh * SEQ * HDIM;
    const float* vbase = g_v + (size_t)bh * SEQ * HDIM;

    u64 q2[32];                                  // 64 floats packed in pairs
#pragma unroll
    for (int i = 0; i < 16; i++) {
        ulonglong2 t2 = *(const ulonglong2*)(qptr + 4*i);
        q2[2*i]   = t2.x;
        q2[2*i+1] = t2.y;
    }

    u64 o2[32];
#pragma unroll
    for (int d = 0; d < 32; d++) o2[d] = 0ull;
    float mrun = -1e30f;
    float lrun = 0.0f;

    for (int j0 = 0; j0 < SEQ; j0 += 16) {
        __syncthreads();
#pragma unroll
        for (int u = 0; u < 2; u++) {
            int idx = threadIdx.x + u * 128;    // 0..255 float4 slots
            int jj  = idx >> 4;
            int dd  = (idx & 15) * 4;
            *(float4*)&Ks[jj][dd] = *(const float4*)(kbase + (size_t)(j0+jj)*HDIM + dd);
            *(float4*)&Vs[jj][dd] = *(const float4*)(vbase + (size_t)(j0+jj)*HDIM + dd);
        }
        __syncthreads();

        float s[16];
#pragma unroll
        for (int j = 0; j < 16; j++) {
            const ulonglong2* K4 = (const ulonglong2*)Ks[j];
            u64 p0 = 0ull, p1 = 0ull, p2 = 0ull, p3 = 0ull;
#pragma unroll
            for (int d4 = 0; d4 < 8; d4++) {
                ulonglong2 ka = K4[2*d4];
                ulonglong2 kb = K4[2*d4+1];
                fma2(p0, q2[4*d4+0], ka.x);
                fma2(p1, q2[4*d4+1], ka.y);
                fma2(p2, q2[4*d4+2], kb.x);
                fma2(p3, q2[4*d4+3], kb.y);
            }
            float2 f0 = unpk2(p0), f1 = unpk2(p1), f2 = unpk2(p2), f3 = unpk2(p3);
            s[j] = (((f0.x + f0.y) + (f1.x + f1.y)) +
                    ((f2.x + f2.y) + (f3.x + f3.y))) * 8.0f;   // * sqrt(head_dim)
        }

        float tm = s[0];
#pragma unroll
        for (int j = 1; j < 16; j++) tm = fmaxf(tm, s[j]);
        float nm = fmaxf(mrun, tm);
        float corr = __expf(mrun - nm);
        lrun *= corr;
        u64 corr2 = bcast2(corr);
#pragma unroll
        for (int d = 0; d < 32; d++) mul2(o2[d], corr2);

#pragma unroll
        for (int j = 0; j < 16; j++) {
            float p = __expf(s[j] - nm);
            lrun += p;
            u64 pb = bcast2(p);
            const ulonglong2* V4 = (const ulonglong2*)Vs[j];
#pragma unroll
            for (int d4 = 0; d4 < 16; d4++) {
                ulonglong2 vv = V4[d4];
                fma2(o2[2*d4],   pb, vv.x);
                fma2(o2[2*d4+1], pb, vv.y);
            }
        }
        mrun = nm;
    }

    float inv = 1.0f / lrun;
    int bb = bh >> 4;
    int hi = bh & 15;
    float* dst = g_attn + ((size_t)bb * SEQ + row) * EMB + hi * HDIM;
#pragma unroll
    for (int d4 = 0; d4 < 16; d4++) {
        float2 fa = unpk2(o2[2*d4]);
        float2 fb = unpk2(o2[2*d4+1]);
        float4 r;
        r.x = fa.x * inv; r.y = fa.y * inv;
        r.z = fb.x * inv; r.w = fb.y * inv;
        *(float4*)(dst + 4*d4) = r;
    }
}

// ---------------------------------------------------------------------------
// Output projection: out[m,n] = sum_k g_attn[m,k] * w_out[n,k]
// ---------------------------------------------------------------------------
__global__ __launch_bounds__(256) void gemm_out_kernel(const float* __restrict__ W,
                                                       float* __restrict__ out) {
    __shared__ float As[8][128];
    __shared__ float Ws[8][128];
    const int K = EMB, N = EMB;
    int tid  = threadIdx.x;
    int m0   = blockIdx.y * 128;
    int n0   = blockIdx.x * 128;
    int lrow = tid >> 1;
    int lcol = (tid & 1) * 4;
    const float* Ag = g_attn + (size_t)(m0 + lrow) * K + lcol;
    const float* Wg = W      + (size_t)(n0 + lrow) * K + lcol;
    int tx = tid & 15, ty = tid >> 4;

    u64 acc2[8][4];
#pragma unroll
    for (int i = 0; i < 8; i++)
#pragma unroll
        for (int j = 0; j < 4; j++) acc2[i][j] = 0ull;

    for (int k0 = 0; k0 < K; k0 += 8) {
        float4 a4 = *(const float4*)(Ag + k0);
        float4 w4 = *(const float4*)(Wg + k0);
        __syncthreads();
        As[lcol+0][lrow] = a4.x; As[lcol+1][lrow] = a4.y;
        As[lcol+2][lrow] = a4.z; As[lcol+3][lrow] = a4.w;
        Ws[lcol+0][lrow] = w4.x; Ws[lcol+1][lrow] = w4.y;
        Ws[lcol+2][lrow] = w4.z; Ws[lcol+3][lrow] = w4.w;
        __syncthreads();
#pragma unroll
        for (int kk = 0; kk < 8; kk++) {
            float4 a0 = *(const float4*)&As[kk][ty*8];
            float4 a1 = *(const float4*)&As[kk][ty*8+4];
            ulonglong2 b0 = *(const ulonglong2*)&Ws[kk][tx*8];
            ulonglong2 b1 = *(const ulonglong2*)&Ws[kk][tx*8+4];
            u64 av[8] = {bcast2(a0.x), bcast2(a0.y), bcast2(a0.z), bcast2(a0.w),
                         bcast2(a1.x), bcast2(a1.y), bcast2(a1.z), bcast2(a1.w)};
            u64 bv[4] = {b0.x, b0.y, b1.x, b1.y};
#pragma unroll
            for (int i = 0; i < 8; i++)
#pragma unroll
                for (int j = 0; j < 4; j++)
                    fma2(acc2[i][j], av[i], bv[j]);
        }
    }

#pragma unroll
    for (int i = 0; i < 8; i++) {
        int m = m0 + ty*8 + i;
        float* dst = out + (size_t)m * N + n0 + tx*8;
        float2 f0 = unpk2(acc2[i][0]);
        float2 f1 = unpk2(acc2[i][1]);
        float2 f2 = unpk2(acc2[i][2]);
        float2 f3 = unpk2(acc2[i][3]);
        float4 r0, r1;
        r0.x = f0.x; r0.y = f0.y; r0.z = f1.x; r0.w = f1.y;
        r1.x = f2.x; r1.y = f2.y; r1.z = f3.x; r1.w = f3.y;
        *(float4*)(dst + 0) = r0;
        *(float4*)(dst + 4) = r1;
    }
}

// ---------------------------------------------------------------------------
extern "C" void kernel_launch(void* const* d_in, const int* in_sizes, int n_in,
                              void* d_out, int out_size) {
    const float* x     = (const float*)d_in[0];   // [B,T,E]
    const float* w_qkv = (const float*)d_in[1];   // [3E,E]
    const float* w_out = (const float*)d_in[2];   // [E,E]
    float* out = (float*)d_out;                   // [B,T,E]

    // 1) QKV projection with fused head-split scatter
    gemm_qkv_kernel<<<dim3(NQKV/128, MROWS/128), 256>>>(x, w_qkv);

    // 2) Flash attention (one thread per query row, f32x2 packed)
    attn_kernel<<<dim3(SEQ/128, BATCH*HEADS), 128>>>();

    // 3) Output projection
    gemm_out_kernel<<<dim3(EMB/128, MROWS/128), 256>>>(w_out, out);
}

// round 4
// speedup vs baseline: 1.4114x; 1.3023x over previous
#include <cuda_runtime.h>
#include <cuda_bf16.h>
#include <cstdint>

#define BATCH 2
#define SEQ   2048
#define EMB   1024
#define HEADS 16
#define HDIM  64
#define MROWS (BATCH*SEQ)   // 4096
#define NQKV  (3*EMB)       // 3072

typedef unsigned long long u64;

// ---------------- scratch (device globals; no runtime alloc) ----------------
__device__ float g_q[BATCH*HEADS*SEQ*HDIM];     // [b,h,t,d] fp32
__device__ float g_k[BATCH*HEADS*SEQ*HDIM];
__device__ float g_v[BATCH*HEADS*SEQ*HDIM];
__device__ float g_attn[BATCH*SEQ*EMB];          // [b,t,(h d)] fp32

__device__ __nv_bfloat16 g_xhi[MROWS*EMB],  g_xlo[MROWS*EMB];
__device__ __nv_bfloat16 g_wqh[NQKV*EMB],   g_wql[NQKV*EMB];
__device__ __nv_bfloat16 g_woh[EMB*EMB],    g_wol[EMB*EMB];
__device__ __nv_bfloat16 g_ahi[MROWS*EMB],  g_alo[MROWS*EMB];

// ---------------- mma.sync helpers (baseline sm_80+ PTX, works at sm_103) ---
__device__ __forceinline__ uint32_t smem_u32(const void* p) {
    uint32_t a;
    asm("{ .reg .u64 t; cvta.to.shared.u64 t, %1; cvt.u32.u64 %0, t; }" : "=r"(a) : "l"(p));
    return a;
}
__device__ __forceinline__ void ldsm_x4(uint32_t* r, uint32_t addr) {
    asm volatile("ldmatrix.sync.aligned.m8n8.x4.shared.b16 {%0,%1,%2,%3}, [%4];"
        : "=r"(r[0]), "=r"(r[1]), "=r"(r[2]), "=r"(r[3]) : "r"(addr));
}
__device__ __forceinline__ void mma16816(float* d, const uint32_t* a, uint32_t b0, uint32_t b1) {
    asm volatile("mma.sync.aligned.m16n8k16.row.col.f32.bf16.bf16.f32 "
        "{%0,%1,%2,%3}, {%4,%5,%6,%7}, {%8,%9}, {%0,%1,%2,%3};"
        : "+f"(d[0]), "+f"(d[1]), "+f"(d[2]), "+f"(d[3])
        : "r"(a[0]), "r"(a[1]), "r"(a[2]), "r"(a[3]), "r"(b0), "r"(b1));
}

// ---------------- fp32 -> bf16 hi/lo split ----------------
// SEL: 0 = x -> g_xhi/g_xlo, 1 = w_qkv -> g_wqh/g_wql,
//      2 = w_out -> g_woh/g_wol, 3 = g_attn -> g_ahi/g_alo
template<int SEL>
__global__ __launch_bounds__(256) void split_kernel(const float* __restrict__ srcp, int n4) {
    const float* src = (SEL == 3) ? (const float*)g_attn : srcp;
    __nv_bfloat16* hi = (SEL==0) ? g_xhi : (SEL==1) ? g_wqh : (SEL==2) ? g_woh : g_ahi;
    __nv_bfloat16* lo = (SEL==0) ? g_xlo : (SEL==1) ? g_wql : (SEL==2) ? g_wol : g_alo;
    int i = blockIdx.x * 256 + threadIdx.x;
    if (i >= n4) return;
    float4 v = ((const float4*)src)[i];
    __nv_bfloat16 h0 = __float2bfloat16(v.x);
    __nv_bfloat16 h1 = __float2bfloat16(v.y);
    __nv_bfloat16 h2 = __float2bfloat16(v.z);
    __nv_bfloat16 h3 = __float2bfloat16(v.w);
    __nv_bfloat16 l0 = __float2bfloat16(v.x - __bfloat162float(h0));
    __nv_bfloat16 l1 = __float2bfloat16(v.y - __bfloat162float(h1));
    __nv_bfloat16 l2 = __float2bfloat16(v.z - __bfloat162float(h2));
    __nv_bfloat16 l3 = __float2bfloat16(v.w - __bfloat162float(h3));
    ushort4 hv, lv;
    hv.x = *(unsigned short*)&h0; hv.y = *(unsigned short*)&h1;
    hv.z = *(unsigned short*)&h2; hv.w = *(unsigned short*)&h3;
    lv.x = *(unsigned short*)&l0; lv.y = *(unsigned short*)&l1;
    lv.z = *(unsigned short*)&l2; lv.w = *(unsigned short*)&l3;
    ((ushort4*)hi)[i] = hv;
    ((ushort4*)lo)[i] = lv;
}

// ---------------- HMMA GEMM: C[m,n] = sum_k A[m,k] * B[n,k] (fp32 via bf16 split)
// Block tile 128x128, 8 warps (warp tile 32x64), k-chunk 64 in padded smem.
// EPI 0: A=x, B=w_qkv, scatter epilogue per (b,t,d,3,h).  EPI 1: A=attn, B=w_out.
#define LDP 72                     // padded row stride (bf16 elems) -> conflict-free ldmatrix
#define GEMM_SMEM (4 * 128 * LDP * 2)   // Ahi, Alo, Bhi, Blo tiles

template<int EPI>
__global__ __launch_bounds__(256) void hmma_gemm(float* __restrict__ Cout) {
    const __nv_bfloat16* Ahi = EPI ? g_ahi : g_xhi;
    const __nv_bfloat16* Alo = EPI ? g_alo : g_xlo;
    const __nv_bfloat16* Bhi = EPI ? g_woh : g_wqh;
    const __nv_bfloat16* Blo = EPI ? g_wol : g_wql;

    extern __shared__ __nv_bfloat16 sm[];
    __nv_bfloat16* As[2] = { sm,               sm + 128*LDP };
    __nv_bfloat16* Bs[2] = { sm + 2*128*LDP,   sm + 3*128*LDP };

    int tid = threadIdx.x, lane = tid & 31, wid = tid >> 5;
    int m0 = blockIdx.y * 128, n0 = blockIdx.x * 128;
    int wm = (wid & 3) * 32;        // warp m-offset in tile
    int wn = (wid >> 2) * 64;       // warp n-offset in tile

    float acc[2][8][4];
#pragma unroll
    for (int i = 0; i < 2; i++)
#pragma unroll
        for (int j = 0; j < 8; j++)
#pragma unroll
            for (int q = 0; q < 4; q++) acc[i][j][q] = 0.0f;

    uint32_t asb[2] = { smem_u32(As[0]), smem_u32(As[1]) };
    uint32_t bsb[2] = { smem_u32(Bs[0]), smem_u32(Bs[1]) };

    for (int k0 = 0; k0 < EMB; k0 += 64) {
        __syncthreads();
        // load 128x64 bf16 tiles for Ahi/Alo/Bhi/Blo (1024 uint4 each / 256 thr)
#pragma unroll
        for (int s = 0; s < 4; s++) {
            int slot = s * 256 + tid;
            int r = slot >> 3, c = (slot & 7) * 8;
            size_t ga = (size_t)(m0 + r) * EMB + k0 + c;
            size_t gb = (size_t)(n0 + r) * EMB + k0 + c;
            *(uint4*)&As[0][r*LDP + c] = *(const uint4*)&Ahi[ga];
            *(uint4*)&As[1][r*LDP + c] = *(const uint4*)&Alo[ga];
            *(uint4*)&Bs[0][r*LDP + c] = *(const uint4*)&Bhi[gb];
            *(uint4*)&Bs[1][r*LDP + c] = *(const uint4*)&Blo[gb];
        }
        __syncthreads();

#pragma unroll
        for (int kc = 0; kc < 64; kc += 16) {
            // A fragments: 2 m16 tiles x {hi,lo}
            uint32_t ah[2][4], al[2][4];
#pragma unroll
            for (int mi = 0; mi < 2; mi++) {
                uint32_t off = (uint32_t)((wm + mi*16 + (lane & 15)) * LDP
                                           + kc + (lane >> 4) * 8) * 2;
                ldsm_x4(ah[mi], asb[0] + off);
                ldsm_x4(al[mi], asb[1] + off);
            }
#pragma unroll
            for (int nj = 0; nj < 4; nj++) {
                // B fragments: n16 (two n8 operands) x {hi,lo}
                uint32_t brow = wn + nj*16 + (lane & 7) + ((lane >> 4) & 1) * 8;
                uint32_t bcol = kc + ((lane >> 3) & 1) * 8;
                uint32_t boff = (uint32_t)(brow * LDP + bcol) * 2;
                uint32_t bh[4], bl[4];
                ldsm_x4(bh, bsb[0] + boff);
                ldsm_x4(bl, bsb[1] + boff);
#pragma unroll
                for (int s2 = 0; s2 < 2; s2++) {
                    uint32_t bh0 = bh[s2*2], bh1 = bh[s2*2+1];
                    uint32_t bl0 = bl[s2*2], bl1 = bl[s2*2+1];
#pragma unroll
                    for (int mi = 0; mi < 2; mi++) {
                        float* d = acc[mi][nj*2 + s2];
                        mma16816(d, ah[mi], bh0, bh1);   // hi*hi
                        mma16816(d, ah[mi], bl0, bl1);   // hi*lo
                        mma16816(d, al[mi], bh0, bh1);   // lo*hi
                    }
                }
            }
        }
    }

    // epilogue: d0,d1 -> row base+(lane>>2), cols 2*(lane&3)+{0,1}; d2,d3 -> row+8
#pragma unroll
    for (int mi = 0; mi < 2; mi++) {
#pragma unroll
        for (int ni = 0; ni < 8; ni++) {
            float* d = acc[mi][ni];
            int mrow0 = m0 + wm + mi*16 + (lane >> 2);
            int ncol0 = n0 + wn + ni*8 + 2*(lane & 3);
            if (EPI == 0) {
#pragma unroll
                for (int h2 = 0; h2 < 2; h2++) {         // d01 vs d23 (row, row+8)
                    int m = mrow0 + h2*8;
                    int bb = m >> 11, t = m & 2047;
#pragma unroll
                    for (int c2 = 0; c2 < 2; c2++) {
                        int n  = ncol0 + c2;
                        int di = n / 48;
                        int ki = (n >> 4) % 3;
                        int hh = n & 15;
                        size_t dst = ((size_t)(bb*HEADS + hh) * SEQ + t) * HDIM + di;
                        float v = d[h2*2 + c2];
                        if (ki == 0)      g_q[dst] = v;
                        else if (ki == 1) g_k[dst] = v;
                        else              g_v[dst] = v;
                    }
                }
            } else {
                float2 r0; r0.x = d[0]; r0.y = d[1];
                float2 r1; r1.x = d[2]; r1.y = d[3];
                *(float2*)&Cout[(size_t)mrow0       * EMB + ncol0] = r0;
                *(float2*)&Cout[(size_t)(mrow0 + 8) * EMB + ncol0] = r1;
            }
        }
    }
}

// ---------------- packed f32x2 helpers ----------------
__device__ __forceinline__ u64 bcast2(float v) {
    u64 r; unsigned u = __float_as_uint(v);
    asm("mov.b64 %0, {%1, %1};" : "=l"(r) : "r"(u));
    return r;
}
__device__ __forceinline__ void fma2(u64& acc, u64 a, u64 b) {
    asm("fma.rn.f32x2 %0, %1, %2, %0;" : "+l"(acc) : "l"(a), "l"(b));
}
__device__ __forceinline__ void mul2(u64& d, u64 a) {
    asm("mul.rn.f32x2 %0, %0, %1;" : "+l"(d) : "l"(a));
}
__device__ __forceinline__ float2 unpk2(u64 v) {
    unsigned lo, hi;
    asm("mov.b64 {%0, %1}, %2;" : "=r"(lo), "=r"(hi) : "l"(v));
    float2 f; f.x = __uint_as_float(lo); f.y = __uint_as_float(hi);
    return f;
}

// ---------------- flash attention (fp32, one thread per query row) ----------
__global__ __launch_bounds__(128, 2) void attn_kernel() {
    __shared__ float Ks[16][64];
    __shared__ float Vs[16][64];

    int bh  = blockIdx.y;
    int row = blockIdx.x * 128 + threadIdx.x;

    const float* qptr  = g_q + ((size_t)bh * SEQ + row) * HDIM;
    const float* kbase = g_k + (size_t)bh * SEQ * HDIM;
    const float* vbase = g_v + (size_t)bh * SEQ * HDIM;

    u64 q2[32];
#pragma unroll
    for (int i = 0; i < 16; i++) {
        ulonglong2 t2 = *(const ulonglong2*)(qptr + 4*i);
        q2[2*i] = t2.x; q2[2*i+1] = t2.y;
    }
    u64 o2[32];
#pragma unroll
    for (int d = 0; d < 32; d++) o2[d] = 0ull;
    float mrun = -1e30f, lrun = 0.0f;

    for (int j0 = 0; j0 < SEQ; j0 += 16) {
        __syncthreads();
#pragma unroll
        for (int u = 0; u < 2; u++) {
            int idx = threadIdx.x + u * 128;
            int jj = idx >> 4, dd = (idx & 15) * 4;
            *(float4*)&Ks[jj][dd] = *(const float4*)(kbase + (size_t)(j0+jj)*HDIM + dd);
            *(float4*)&Vs[jj][dd] = *(const float4*)(vbase + (size_t)(j0+jj)*HDIM + dd);
        }
        __syncthreads();

        float s[16];
#pragma unroll
        for (int j = 0; j < 16; j++) {
            const ulonglong2* K4 = (const ulonglong2*)Ks[j];
            u64 p0 = 0ull, p1 = 0ull, p2 = 0ull, p3 = 0ull;
#pragma unroll
            for (int d4 = 0; d4 < 8; d4++) {
                ulonglong2 ka = K4[2*d4], kb = K4[2*d4+1];
                fma2(p0, q2[4*d4+0], ka.x);
                fma2(p1, q2[4*d4+1], ka.y);
                fma2(p2, q2[4*d4+2], kb.x);
                fma2(p3, q2[4*d4+3], kb.y);
            }
            float2 f0 = unpk2(p0), f1 = unpk2(p1), f2 = unpk2(p2), f3 = unpk2(p3);
            s[j] = (((f0.x + f0.y) + (f1.x + f1.y)) +
                    ((f2.x + f2.y) + (f3.x + f3.y))) * 8.0f;   // * sqrt(d)
        }
        float tm = s[0];
#pragma unroll
        for (int j = 1; j < 16; j++) tm = fmaxf(tm, s[j]);
        float nm = fmaxf(mrun, tm);
        float corr = __expf(mrun - nm);
        lrun *= corr;
        u64 corr2 = bcast2(corr);
#pragma unroll
        for (int d = 0; d < 32; d++) mul2(o2[d], corr2);
#pragma unroll
        for (int j = 0; j < 16; j++) {
            float p = __expf(s[j] - nm);
            lrun += p;
            u64 pb = bcast2(p);
            const ulonglong2* V4 = (const ulonglong2*)Vs[j];
#pragma unroll
            for (int d4 = 0; d4 < 16; d4++) {
                ulonglong2 vv = V4[d4];
                fma2(o2[2*d4],   pb, vv.x);
                fma2(o2[2*d4+1], pb, vv.y);
            }
        }
        mrun = nm;
    }

    float inv = 1.0f / lrun;
    int bb = bh >> 4, hi = bh & 15;
    float* dst = g_attn + ((size_t)bb * SEQ + row) * EMB + hi * HDIM;
#pragma unroll
    for (int d4 = 0; d4 < 16; d4++) {
        float2 fa = unpk2(o2[2*d4]), fb = unpk2(o2[2*d4+1]);
        float4 r; r.x = fa.x*inv; r.y = fa.y*inv; r.z = fb.x*inv; r.w = fb.y*inv;
        *(float4*)(dst + 4*d4) = r;
    }
}

// ---------------------------------------------------------------------------
extern "C" void kernel_launch(void* const* d_in, const int* in_sizes, int n_in,
                              void* d_out, int out_size) {
    const float* x     = (const float*)d_in[0];   // [B,T,E]
    const float* w_qkv = (const float*)d_in[1];   // [3E,E]
    const float* w_out = (const float*)d_in[2];   // [E,E]
    float* out = (float*)d_out;                   // [B,T,E]

    cudaFuncSetAttribute(hmma_gemm<0>, cudaFuncAttributeMaxDynamicSharedMemorySize, GEMM_SMEM);
    cudaFuncSetAttribute(hmma_gemm<1>, cudaFuncAttributeMaxDynamicSharedMemorySize, GEMM_SMEM);

    // 1) split inputs to bf16 hi/lo
    split_kernel<0><<<(MROWS*EMB/4 + 255)/256, 256>>>(x,     MROWS*EMB/4);
    split_kernel<1><<<(NQKV*EMB/4  + 255)/256, 256>>>(w_qkv, NQKV*EMB/4);
    split_kernel<2><<<(EMB*EMB/4   + 255)/256, 256>>>(w_out, EMB*EMB/4);

    // 2) QKV projection (HMMA, bf16 split) with fused head-split scatter
    hmma_gemm<0><<<dim3(NQKV/128, MROWS/128), 256, GEMM_SMEM>>>(nullptr);

    // 3) Flash attention
    attn_kernel<<<dim3(SEQ/128, BATCH*HEADS), 128>>>();

    // 4) split attention output, then output projection (HMMA)
    split_kernel<3><<<(MROWS*EMB/4 + 255)/256, 256>>>(nullptr, MROWS*EMB/4);
    hmma_gemm<1><<<dim3(EMB/128, MROWS/128), 256, GEMM_SMEM>>>(out);
}

// round 5
// speedup vs baseline: 2.6379x; 1.8689x over previous
#include <cuda_runtime.h>
#include <cuda_bf16.h>
#include <cstdint>

#define BATCH 2
#define SEQ   2048
#define EMB   1024
#define HEADS 16
#define HDIM  64
#define MROWS (BATCH*SEQ)   // 4096
#define NQKV  (3*EMB)       // 3072
#define QKVN  (BATCH*HEADS*SEQ*HDIM)

// ---------------- scratch (device globals; no runtime alloc) ----------------
__device__ float g_attn[MROWS*EMB];              // [b,t,(h d)] fp32

__device__ __nv_bfloat16 g_xhi[MROWS*EMB],  g_xlo[MROWS*EMB];
__device__ __nv_bfloat16 g_wqh[NQKV*EMB],   g_wql[NQKV*EMB];
__device__ __nv_bfloat16 g_woh[EMB*EMB],    g_wol[EMB*EMB];
__device__ __nv_bfloat16 g_ahi[MROWS*EMB],  g_alo[MROWS*EMB];

__device__ __nv_bfloat16 g_qh[QKVN], g_ql[QKVN];   // [b,h,t,d]
__device__ __nv_bfloat16 g_kh[QKVN], g_kl[QKVN];   // [b,h,t,d]
__device__ __nv_bfloat16 g_vth[QKVN], g_vtl[QKVN]; // [b,h,d,t]  (transposed)

// ---------------- mma.sync helpers (baseline sm_80+ PTX) ----------------
__device__ __forceinline__ uint32_t smem_u32(const void* p) {
    uint32_t a;
    asm("{ .reg .u64 t; cvta.to.shared.u64 t, %1; cvt.u32.u64 %0, t; }" : "=r"(a) : "l"(p));
    return a;
}
__device__ __forceinline__ void ldsm_x4(uint32_t* r, uint32_t addr) {
    asm volatile("ldmatrix.sync.aligned.m8n8.x4.shared.b16 {%0,%1,%2,%3}, [%4];"
        : "=r"(r[0]), "=r"(r[1]), "=r"(r[2]), "=r"(r[3]) : "r"(addr));
}
__device__ __forceinline__ void mma16816(float* d, const uint32_t* a, uint32_t b0, uint32_t b1) {
    asm volatile("mma.sync.aligned.m16n8k16.row.col.f32.bf16.bf16.f32 "
        "{%0,%1,%2,%3}, {%4,%5,%6,%7}, {%8,%9}, {%0,%1,%2,%3};"
        : "+f"(d[0]), "+f"(d[1]), "+f"(d[2]), "+f"(d[3])
        : "r"(a[0]), "r"(a[1]), "r"(a[2]), "r"(a[3]), "r"(b0), "r"(b1));
}
// pack (x,y) -> bf16x2 hi, and return residual bf16x2 lo
__device__ __forceinline__ uint32_t packsplit(float x, float y, uint32_t& lo) {
    uint32_t hp;
    asm("cvt.rn.bf16x2.f32 %0, %1, %2;" : "=r"(hp) : "f"(y), "f"(x));
    float hx = __uint_as_float(hp << 16);
    float hy = __uint_as_float(hp & 0xffff0000u);
    float lx = x - hx, ly = y - hy;
    asm("cvt.rn.bf16x2.f32 %0, %1, %2;" : "=r"(lo) : "f"(ly), "f"(lx));
    return hp;
}
// fast 2^t on FMA pipe (t <= 0 in all uses); |rel err| ~ 2.4e-6
__device__ __forceinline__ float e2(float t) {
    t = fmaxf(t, -124.0f);
    int i = __float2int_rn(t);
    float f = t - (float)i;                    // [-0.5, 0.5]
    float p = 1.3333558146e-3f;                // ln2^5/120
    p = fmaf(p, f, 9.6181291076e-3f);          // ln2^4/24
    p = fmaf(p, f, 5.5504108664e-2f);          // ln2^3/6
    p = fmaf(p, f, 2.4022650696e-1f);          // ln2^2/2
    p = fmaf(p, f, 6.9314718056e-1f);          // ln2
    p = fmaf(p, f, 1.0f);
    return __int_as_float((i << 23) + __float_as_int(p));
}
#define EXPSCALE 11.541560327111707f   // 8 * log2(e)

// ---------------- fp32 -> bf16 hi/lo split ----------------
template<int SEL>
__global__ __launch_bounds__(256) void split_kernel(const float* __restrict__ srcp, int n4) {
    const float* src = (SEL == 3) ? (const float*)g_attn : srcp;
    __nv_bfloat16* hi = (SEL==0) ? g_xhi : (SEL==1) ? g_wqh : (SEL==2) ? g_woh : g_ahi;
    __nv_bfloat16* lo = (SEL==0) ? g_xlo : (SEL==1) ? g_wql : (SEL==2) ? g_wol : g_alo;
    int i = blockIdx.x * 256 + threadIdx.x;
    if (i >= n4) return;
    float4 v = ((const float4*)src)[i];
    __nv_bfloat16 h0 = __float2bfloat16(v.x);
    __nv_bfloat16 h1 = __float2bfloat16(v.y);
    __nv_bfloat16 h2 = __float2bfloat16(v.z);
    __nv_bfloat16 h3 = __float2bfloat16(v.w);
    __nv_bfloat16 l0 = __float2bfloat16(v.x - __bfloat162float(h0));
    __nv_bfloat16 l1 = __float2bfloat16(v.y - __bfloat162float(h1));
    __nv_bfloat16 l2 = __float2bfloat16(v.z - __bfloat162float(h2));
    __nv_bfloat16 l3 = __float2bfloat16(v.w - __bfloat162float(h3));
    ushort4 hv, lv;
    hv.x = *(unsigned short*)&h0; hv.y = *(unsigned short*)&h1;
    hv.z = *(unsigned short*)&h2; hv.w = *(unsigned short*)&h3;
    lv.x = *(unsigned short*)&l0; lv.y = *(unsigned short*)&l1;
    lv.z = *(unsigned short*)&l2; lv.w = *(unsigned short*)&l3;
    ((ushort4*)hi)[i] = hv;
    ((ushort4*)lo)[i] = lv;
}

// ---------------- HMMA GEMM (bf16 split, 3-term) ----------------
#define LDP 72
#define GEMM_SMEM (4 * 128 * LDP * 2)

template<int EPI>
__global__ __launch_bounds__(256) void hmma_gemm(float* __restrict__ Cout) {
    const __nv_bfloat16* Ahi = EPI ? g_ahi : g_xhi;
    const __nv_bfloat16* Alo = EPI ? g_alo : g_xlo;
    const __nv_bfloat16* Bhi = EPI ? g_woh : g_wqh;
    const __nv_bfloat16* Blo = EPI ? g_wol : g_wql;

    extern __shared__ __nv_bfloat16 sm[];
    __nv_bfloat16* As[2] = { sm,               sm + 128*LDP };
    __nv_bfloat16* Bs[2] = { sm + 2*128*LDP,   sm + 3*128*LDP };

    int tid = threadIdx.x, lane = tid & 31, wid = tid >> 5;
    int m0 = blockIdx.y * 128, n0 = blockIdx.x * 128;
    int wm = (wid & 3) * 32;
    int wn = (wid >> 2) * 64;

    float acc[2][8][4];
#pragma unroll
    for (int i = 0; i < 2; i++)
#pragma unroll
        for (int j = 0; j < 8; j++)
#pragma unroll
            for (int q = 0; q < 4; q++) acc[i][j][q] = 0.0f;

    uint32_t asb[2] = { smem_u32(As[0]), smem_u32(As[1]) };
    uint32_t bsb[2] = { smem_u32(Bs[0]), smem_u32(Bs[1]) };

    for (int k0 = 0; k0 < EMB; k0 += 64) {
        __syncthreads();
#pragma unroll
        for (int s = 0; s < 4; s++) {
            int slot = s * 256 + tid;
            int r = slot >> 3, c = (slot & 7) * 8;
            size_t ga = (size_t)(m0 + r) * EMB + k0 + c;
            size_t gb = (size_t)(n0 + r) * EMB + k0 + c;
            *(uint4*)&As[0][r*LDP + c] = *(const uint4*)&Ahi[ga];
            *(uint4*)&As[1][r*LDP + c] = *(const uint4*)&Alo[ga];
            *(uint4*)&Bs[0][r*LDP + c] = *(const uint4*)&Bhi[gb];
            *(uint4*)&Bs[1][r*LDP + c] = *(const uint4*)&Blo[gb];
        }
        __syncthreads();

#pragma unroll
        for (int kc = 0; kc < 64; kc += 16) {
            uint32_t ah[2][4], al[2][4];
#pragma unroll
            for (int mi = 0; mi < 2; mi++) {
                uint32_t off = (uint32_t)((wm + mi*16 + (lane & 15)) * LDP
                                           + kc + (lane >> 4) * 8) * 2;
                ldsm_x4(ah[mi], asb[0] + off);
                ldsm_x4(al[mi], asb[1] + off);
            }
#pragma unroll
            for (int nj = 0; nj < 4; nj++) {
                uint32_t brow = wn + nj*16 + (lane & 7) + ((lane >> 4) & 1) * 8;
                uint32_t bcol = kc + ((lane >> 3) & 1) * 8;
                uint32_t boff = (uint32_t)(brow * LDP + bcol) * 2;
                uint32_t bh[4], bl[4];
                ldsm_x4(bh, bsb[0] + boff);
                ldsm_x4(bl, bsb[1] + boff);
#pragma unroll
                for (int s2 = 0; s2 < 2; s2++) {
#pragma unroll
                    for (int mi = 0; mi < 2; mi++) {
                        float* d = acc[mi][nj*2 + s2];
                        mma16816(d, ah[mi], bh[s2*2], bh[s2*2+1]);
                        mma16816(d, ah[mi], bl[s2*2], bl[s2*2+1]);
                        mma16816(d, al[mi], bh[s2*2], bh[s2*2+1]);
                    }
                }
            }
        }
    }

#pragma unroll
    for (int mi = 0; mi < 2; mi++) {
#pragma unroll
        for (int ni = 0; ni < 8; ni++) {
            float* d = acc[mi][ni];
            int mrow0 = m0 + wm + mi*16 + (lane >> 2);
            int ncol0 = n0 + wn + ni*8 + 2*(lane & 3);
            if (EPI == 0) {
#pragma unroll
                for (int h2 = 0; h2 < 2; h2++) {
                    int m = mrow0 + h2*8;
                    int bb = m >> 11, t = m & 2047;
#pragma unroll
                    for (int c2 = 0; c2 < 2; c2++) {
                        int n  = ncol0 + c2;
                        int di = n / 48;
                        int ki = (n >> 4) % 3;
                        int hh = n & 15;
                        float v = d[h2*2 + c2];
                        __nv_bfloat16 hb = __float2bfloat16(v);
                        __nv_bfloat16 lb = __float2bfloat16(v - __bfloat162float(hb));
                        if (ki == 2) {
                            size_t dst = ((size_t)(bb*HEADS + hh) * HDIM + di) * SEQ + t;
                            g_vth[dst] = hb; g_vtl[dst] = lb;
                        } else {
                            size_t dst = ((size_t)(bb*HEADS + hh) * SEQ + t) * HDIM + di;
                            if (ki == 0) { g_qh[dst] = hb; g_ql[dst] = lb; }
                            else         { g_kh[dst] = hb; g_kl[dst] = lb; }
                        }
                    }
                }
            } else {
                float2 r0; r0.x = d[0]; r0.y = d[1];
                float2 r1; r1.x = d[2]; r1.y = d[3];
                *(float2*)&Cout[(size_t)mrow0       * EMB + ncol0] = r0;
                *(float2*)&Cout[(size_t)(mrow0 + 8) * EMB + ncol0] = r1;
            }
        }
    }
}

// ---------------- HMMA flash attention ----------------
// CTA: 128 q-rows, 4 warps (32 rows each). Key tiles of 64. bf16 hi/lo 3-term
// for both QK^T and P@V; online softmax with FMA-pipe exp2 polynomial.
#define ALDP 72
#define ATT_SMEM ((2*128 + 4*64) * ALDP * 2)

__global__ __launch_bounds__(128) void attn_hmma() {
    extern __shared__ __nv_bfloat16 sm[];
    __nv_bfloat16 *Qh = sm,              *Ql = Qh + 128*ALDP;
    __nv_bfloat16 *Kh = Ql + 128*ALDP,   *Kl = Kh + 64*ALDP;
    __nv_bfloat16 *Vh = Kl + 64*ALDP,    *Vl = Vh + 64*ALDP;

    int tid = threadIdx.x, lane = tid & 31, wid = tid >> 5;
    int bh = blockIdx.y, q0 = blockIdx.x * 128;
    int wm = wid * 32;

    size_t qgbase = ((size_t)bh * SEQ + q0) * HDIM;
#pragma unroll
    for (int i = 0; i < 8; i++) {
        int slot = i * 128 + tid;
        int r = slot >> 3, c = (slot & 7) * 8;
        *(uint4*)&Qh[r*ALDP + c] = *(const uint4*)&g_qh[qgbase + (size_t)r*HDIM + c];
        *(uint4*)&Ql[r*ALDP + c] = *(const uint4*)&g_ql[qgbase + (size_t)r*HDIM + c];
    }

    float O[2][8][4];
#pragma unroll
    for (int i = 0; i < 2; i++)
#pragma unroll
        for (int j = 0; j < 8; j++)
#pragma unroll
            for (int q = 0; q < 4; q++) O[i][j][q] = 0.0f;
    float lacc[4] = {0.f, 0.f, 0.f, 0.f};
    float mrun[4] = {-1e30f, -1e30f, -1e30f, -1e30f};

    uint32_t qsbh = smem_u32(Qh), qsbl = smem_u32(Ql);
    uint32_t ksbh = smem_u32(Kh), ksbl = smem_u32(Kl);
    uint32_t vsbh = smem_u32(Vh), vsbl = smem_u32(Vl);

    const size_t kgbase = (size_t)bh * SEQ * HDIM;
    const size_t vgbase = (size_t)bh * HDIM * SEQ;

    for (int kt = 0; kt < SEQ/64; kt++) {
        __syncthreads();
#pragma unroll
        for (int i = 0; i < 4; i++) {
            int slot = i * 128 + tid;                  // 0..511
            int r = slot >> 3, c = (slot & 7) * 8;
            *(uint4*)&Kh[r*ALDP + c] = *(const uint4*)&g_kh[kgbase + (size_t)(kt*64 + r)*HDIM + c];
            *(uint4*)&Kl[r*ALDP + c] = *(const uint4*)&g_kl[kgbase + (size_t)(kt*64 + r)*HDIM + c];
            *(uint4*)&Vh[r*ALDP + c] = *(const uint4*)&g_vth[vgbase + (size_t)r*SEQ + kt*64 + c];
            *(uint4*)&Vl[r*ALDP + c] = *(const uint4*)&g_vtl[vgbase + (size_t)r*SEQ + kt*64 + c];
        }
        __syncthreads();

        // ---- S = Q K^T (raw dot; scale folded into exp) ----
        float S[2][8][4];
#pragma unroll
        for (int i = 0; i < 2; i++)
#pragma unroll
            for (int j = 0; j < 8; j++)
#pragma unroll
                for (int q = 0; q < 4; q++) S[i][j][q] = 0.0f;

#pragma unroll
        for (int ks = 0; ks < 4; ks++) {
            uint32_t qh[2][4], ql[2][4];
#pragma unroll
            for (int mi = 0; mi < 2; mi++) {
                uint32_t off = (uint32_t)((wm + mi*16 + (lane & 15)) * ALDP
                                           + ks*16 + (lane >> 4) * 8) * 2;
                ldsm_x4(qh[mi], qsbh + off);
                ldsm_x4(ql[mi], qsbl + off);
            }
#pragma unroll
            for (int nj = 0; nj < 4; nj++) {
                uint32_t boff = (uint32_t)((nj*16 + (lane & 7) + ((lane >> 4) & 1) * 8) * ALDP
                                           + ks*16 + ((lane >> 3) & 1) * 8) * 2;
                uint32_t kh[4], kl[4];
                ldsm_x4(kh, ksbh + boff);
                ldsm_x4(kl, ksbl + boff);
#pragma unroll
                for (int s2 = 0; s2 < 2; s2++) {
#pragma unroll
                    for (int mi = 0; mi < 2; mi++) {
                        float* d = S[mi][nj*2 + s2];
                        mma16816(d, qh[mi], kh[s2*2], kh[s2*2+1]);
                        mma16816(d, qh[mi], kl[s2*2], kl[s2*2+1]);
                        mma16816(d, ql[mi], kh[s2*2], kh[s2*2+1]);
                    }
                }
            }
        }

        // ---- online softmax (row = lane>>2 (+8); 4 lanes per row) ----
        float tmx[4] = {-1e30f, -1e30f, -1e30f, -1e30f};
#pragma unroll
        for (int mi = 0; mi < 2; mi++)
#pragma unroll
            for (int ni = 0; ni < 8; ni++) {
                tmx[mi*2+0] = fmaxf(tmx[mi*2+0], fmaxf(S[mi][ni][0], S[mi][ni][1]));
                tmx[mi*2+1] = fmaxf(tmx[mi*2+1], fmaxf(S[mi][ni][2], S[mi][ni][3]));
            }
#pragma unroll
        for (int i = 0; i < 4; i++) {
            tmx[i] = fmaxf(tmx[i], __shfl_xor_sync(0xffffffffu, tmx[i], 1));
            tmx[i] = fmaxf(tmx[i], __shfl_xor_sync(0xffffffffu, tmx[i], 2));
        }
        float corr[4];
#pragma unroll
        for (int i = 0; i < 4; i++) {
            float mn = fmaxf(mrun[i], tmx[i]);
            corr[i] = e2((mrun[i] - mn) * EXPSCALE);
            mrun[i] = mn;
            lacc[i] *= corr[i];
        }
#pragma unroll
        for (int mi = 0; mi < 2; mi++)
#pragma unroll
            for (int ni = 0; ni < 8; ni++) {
                O[mi][ni][0] *= corr[mi*2+0];
                O[mi][ni][1] *= corr[mi*2+0];
                O[mi][ni][2] *= corr[mi*2+1];
                O[mi][ni][3] *= corr[mi*2+1];
            }
#pragma unroll
        for (int mi = 0; mi < 2; mi++)
#pragma unroll
            for (int ni = 0; ni < 8; ni++) {
                float p0 = e2((S[mi][ni][0] - mrun[mi*2+0]) * EXPSCALE);
                float p1 = e2((S[mi][ni][1] - mrun[mi*2+0]) * EXPSCALE);
                float p2 = e2((S[mi][ni][2] - mrun[mi*2+1]) * EXPSCALE);
                float p3 = e2((S[mi][ni][3] - mrun[mi*2+1]) * EXPSCALE);
                S[mi][ni][0] = p0; S[mi][ni][1] = p1;
                S[mi][ni][2] = p2; S[mi][ni][3] = p3;
                lacc[mi*2+0] += p0 + p1;
                lacc[mi*2+1] += p2 + p3;
            }

        // ---- O += P @ V  (P repacked from accumulator; V^T tile in smem) ----
#pragma unroll
        for (int ks = 0; ks < 4; ks++) {
            uint32_t pah[2][4], pal[2][4];
#pragma unroll
            for (int mi = 0; mi < 2; mi++) {
                pah[mi][0] = packsplit(S[mi][2*ks  ][0], S[mi][2*ks  ][1], pal[mi][0]);
                pah[mi][1] = packsplit(S[mi][2*ks  ][2], S[mi][2*ks  ][3], pal[mi][1]);
                pah[mi][2] = packsplit(S[mi][2*ks+1][0], S[mi][2*ks+1][1], pal[mi][2]);
                pah[mi][3] = packsplit(S[mi][2*ks+1][2], S[mi][2*ks+1][3], pal[mi][3]);
            }
#pragma unroll
            for (int dj = 0; dj < 4; dj++) {
                uint32_t boff = (uint32_t)((dj*16 + (lane & 7) + ((lane >> 4) & 1) * 8) * ALDP
                                           + ks*16 + ((lane >> 3) & 1) * 8) * 2;
                uint32_t vh[4], vl[4];
                ldsm_x4(vh, vsbh + boff);
                ldsm_x4(vl, vsbl + boff);
#pragma unroll
                for (int s2 = 0; s2 < 2; s2++) {
#pragma unroll
                    for (int mi = 0; mi < 2; mi++) {
                        float* d = O[mi][dj*2 + s2];
                        mma16816(d, pah[mi], vh[s2*2], vh[s2*2+1]);
                        mma16816(d, pah[mi], vl[s2*2], vl[s2*2+1]);
                        mma16816(d, pal[mi], vh[s2*2], vh[s2*2+1]);
                    }
                }
            }
        }
    }

    // ---- finalize: divide by l, write fp32 ----
    float inv[4];
#pragma unroll
    for (int i = 0; i < 4; i++) {
        lacc[i] += __shfl_xor_sync(0xffffffffu, lacc[i], 1);
        lacc[i] += __shfl_xor_sync(0xffffffffu, lacc[i], 2);
        inv[i] = 1.0f / lacc[i];
    }
    int b = bh >> 4, h = bh & 15;
#pragma unroll
    for (int mi = 0; mi < 2; mi++) {
#pragma unroll
        for (int h2 = 0; h2 < 2; h2++) {
            int m = q0 + wm + mi*16 + (lane >> 2) + h2*8;
            float* dst = g_attn + ((size_t)b * SEQ + m) * EMB + h * HDIM;
            float iv = inv[mi*2 + h2];
#pragma unroll
            for (int ni = 0; ni < 8; ni++) {
                float2 r;
                r.x = O[mi][ni][h2*2+0] * iv;
                r.y = O[mi][ni][h2*2+1] * iv;
                *(float2*)&dst[ni*8 + 2*(lane & 3)] = r;
            }
        }
    }
}

// ---------------------------------------------------------------------------
extern "C" void kernel_launch(void* const* d_in, const int* in_sizes, int n_in,
                              void* d_out, int out_size) {
    const float* x     = (const float*)d_in[0];   // [B,T,E]
    const float* w_qkv = (const float*)d_in[1];   // [3E,E]
    const float* w_out = (const float*)d_in[2];   // [E,E]
    float* out = (float*)d_out;                   // [B,T,E]

    cudaFuncSetAttribute(hmma_gemm<0>, cudaFuncAttributeMaxDynamicSharedMemorySize, GEMM_SMEM);
    cudaFuncSetAttribute(hmma_gemm<1>, cudaFuncAttributeMaxDynamicSharedMemorySize, GEMM_SMEM);
    cudaFuncSetAttribute(attn_hmma,    cudaFuncAttributeMaxDynamicSharedMemorySize, ATT_SMEM);

    // 1) split inputs to bf16 hi/lo
    split_kernel<0><<<(MROWS*EMB/4 + 255)/256, 256>>>(x,     MROWS*EMB/4);
    split_kernel<1><<<(NQKV*EMB/4  + 255)/256, 256>>>(w_qkv, NQKV*EMB/4);
    split_kernel<2><<<(EMB*EMB/4   + 255)/256, 256>>>(w_out, EMB*EMB/4);

    // 2) QKV projection (HMMA) writing q/k hi-lo [b,h,t,d] and v^T hi-lo [b,h,d,t]
    hmma_gemm<0><<<dim3(NQKV/128, MROWS/128), 256, GEMM_SMEM>>>(nullptr);

    // 3) HMMA flash attention
    attn_hmma<<<dim3(SEQ/128, BATCH*HEADS), 128, ATT_SMEM>>>();

    // 4) split attention output, then output projection (HMMA)
    split_kernel<3><<<(MROWS*EMB/4 + 255)/256, 256>>>(nullptr, MROWS*EMB/4);
    hmma_gemm<1><<<dim3(EMB/128, MROWS/128), 256, GEMM_SMEM>>>(out);
}